// round 2
// baseline (speedup 1.0000x reference)
#include <cuda_runtime.h>
#include <math.h>

#define NTOK 4096
#define DIM  1024
#define HDIM 4096
#define NEXP 8
#define NPAIR (NTOK * 2)

// ---------------- scratch (static device globals; no runtime allocation) ----
__device__ float g_h_sh[(size_t)NTOK * HDIM];      // shared-expert hidden, 67MB
__device__ float g_h_rt[(size_t)NPAIR * HDIM];     // routed hidden (compact, permuted), 134MB
__device__ float g_pair_out[(size_t)NPAIR * DIM];  // routed down outputs, 33.5MB
__device__ float g_pair_prob[NPAIR];
__device__ int   g_pair_token[NPAIR];
__device__ int   g_pair_pos[NPAIR];                // [token*2 + slot] -> compact pos
__device__ int   g_topk_idx[NPAIR];
__device__ float g_topk_p[NPAIR];
__device__ int   g_counts[NEXP];
__device__ int   g_offsets[NEXP];
__device__ int   g_cursor[NEXP];

// ---------------- tiny kernels ----------------------------------------------
__global__ void zero_counts_kernel() {
    if (threadIdx.x < NEXP) g_counts[threadIdx.x] = 0;
}

// one warp per token: logits -> sigmoid -> top2 -> normalized probs
__global__ void router_kernel(const float* __restrict__ x,
                              const float* __restrict__ Wr) {
    int gw   = (blockIdx.x * blockDim.x + threadIdx.x) >> 5;
    int lane = threadIdx.x & 31;
    if (gw >= NTOK) return;
    const float* xr = x + (size_t)gw * DIM;
    float acc[NEXP];
#pragma unroll
    for (int e = 0; e < NEXP; e++) acc[e] = 0.f;
    for (int d = lane; d < DIM; d += 32) {
        float xv = xr[d];
        const float* w = Wr + (size_t)d * NEXP;
#pragma unroll
        for (int e = 0; e < NEXP; e++) acc[e] += xv * w[e];
    }
#pragma unroll
    for (int off = 16; off > 0; off >>= 1) {
#pragma unroll
        for (int e = 0; e < NEXP; e++)
            acc[e] += __shfl_xor_sync(0xffffffffu, acc[e], off);
    }
    if (lane == 0) {
        float p[NEXP];
#pragma unroll
        for (int e = 0; e < NEXP; e++) p[e] = 1.f / (1.f + expf(-acc[e]));
        float p1 = -1.f, p2 = -1.f; int i1 = 0, i2 = 0;
#pragma unroll
        for (int e = 0; e < NEXP; e++) {
            float v = p[e];
            if (v > p1)      { p2 = p1; i2 = i1; p1 = v; i1 = e; }
            else if (v > p2) { p2 = v;  i2 = e; }
        }
        float s = p1 + p2 + 1e-6f;
        p1 /= s; p2 /= s;
        g_topk_idx[2 * gw]     = i1;  g_topk_idx[2 * gw + 1] = i2;
        g_topk_p[2 * gw]       = p1;  g_topk_p[2 * gw + 1]   = p2;
        atomicAdd(&g_counts[i1], 1);
        atomicAdd(&g_counts[i2], 1);
    }
}

__global__ void prefix_kernel() {
    if (threadIdx.x == 0) {
        int s = 0;
        for (int e = 0; e < NEXP; e++) {
            g_offsets[e] = s; g_cursor[e] = s; s += g_counts[e];
        }
    }
}

__global__ void scatter_kernel() {
    int n = blockIdx.x * blockDim.x + threadIdx.x;
    if (n >= NTOK) return;
#pragma unroll
    for (int j = 0; j < 2; j++) {
        int e = g_topk_idx[2 * n + j];
        int pos = atomicAdd(&g_cursor[e], 1);
        g_pair_token[pos] = n;
        g_pair_prob[pos]  = g_topk_p[2 * n + j];
        g_pair_pos[2 * n + j] = pos;
    }
}

// ---------------- tiled fp32 GEMMs ------------------------------------------
// 128x128 C-tile, K-step 16, 256 threads, 8x8 per-thread microtile.

// Hout[rowBase+row] = sq_relu( X[token(row)] @ W_e )   (W: [., DIM, HDIM])
__global__ void __launch_bounds__(256, 2)
gemm_up_kernel(const float* __restrict__ X, const float* __restrict__ W,
               float* __restrict__ Hout, int routed) {
    int e = blockIdx.z;
    int rows, rowBase;
    if (routed) { rows = g_counts[e]; rowBase = g_offsets[e]; }
    else        { rows = NTOK;        rowBase = 0; }
    int rowTile = blockIdx.y * 128;
    if (rowTile >= rows) return;
    int colTile = blockIdx.x * 128;
    const float* Wp = W + (size_t)e * DIM * HDIM;

    __shared__ float As[16][128];
    __shared__ float Bs[16][128];

    int tid = threadIdx.x;
    int tr = tid >> 4, tc = tid & 15;

    // A-load mapping: two rows per thread
    int ar0 = tid >> 2;
    int ak  = (tid & 3) * 4;
    int gr0 = rowTile + ar0, gr1 = rowTile + ar0 + 64;
    int t0 = -1, t1 = -1;
    if (gr0 < rows) t0 = routed ? g_pair_token[rowBase + gr0] : gr0;
    if (gr1 < rows) t1 = routed ? g_pair_token[rowBase + gr1] : gr1;
    // B-load mapping
    int bk0 = tid >> 5;
    int bn  = (tid & 31) * 4;

    float acc[8][8];
#pragma unroll
    for (int i = 0; i < 8; i++)
#pragma unroll
        for (int j = 0; j < 8; j++) acc[i][j] = 0.f;

    for (int k0 = 0; k0 < DIM; k0 += 16) {
        float4 a0 = make_float4(0.f, 0.f, 0.f, 0.f), a1 = a0;
        if (t0 >= 0) a0 = *(const float4*)(X + (size_t)t0 * DIM + k0 + ak);
        if (t1 >= 0) a1 = *(const float4*)(X + (size_t)t1 * DIM + k0 + ak);
        const float* Bp = Wp + (size_t)(k0 + bk0) * HDIM + colTile + bn;
        float4 b0 = *(const float4*)Bp;
        float4 b1 = *(const float4*)(Bp + (size_t)8 * HDIM);
        __syncthreads();
        As[ak + 0][ar0] = a0.x; As[ak + 1][ar0] = a0.y;
        As[ak + 2][ar0] = a0.z; As[ak + 3][ar0] = a0.w;
        As[ak + 0][ar0 + 64] = a1.x; As[ak + 1][ar0 + 64] = a1.y;
        As[ak + 2][ar0 + 64] = a1.z; As[ak + 3][ar0 + 64] = a1.w;
        *(float4*)&Bs[bk0][bn]     = b0;
        *(float4*)&Bs[bk0 + 8][bn] = b1;
        __syncthreads();
#pragma unroll
        for (int kk = 0; kk < 16; kk++) {
            float ra[8], rb[8];
            *(float4*)&ra[0] = *(const float4*)&As[kk][tr * 8];
            *(float4*)&ra[4] = *(const float4*)&As[kk][tr * 8 + 4];
            *(float4*)&rb[0] = *(const float4*)&Bs[kk][tc * 8];
            *(float4*)&rb[4] = *(const float4*)&Bs[kk][tc * 8 + 4];
#pragma unroll
            for (int i = 0; i < 8; i++)
#pragma unroll
                for (int j = 0; j < 8; j++) acc[i][j] += ra[i] * rb[j];
        }
    }
#pragma unroll
    for (int i = 0; i < 8; i++) {
        int gr = rowTile + tr * 8 + i;
        if (gr < rows) {
            float* o = Hout + (size_t)(rowBase + gr) * HDIM + colTile + tc * 8;
            float v[8];
#pragma unroll
            for (int j = 0; j < 8; j++) {
                float r = fmaxf(acc[i][j], 0.f);
                v[j] = r * r;
            }
            *(float4*)&o[0] = *(float4*)&v[0];
            *(float4*)&o[4] = *(float4*)&v[4];
        }
    }
}

// Out[rowBase+row] = scale(row) * ( Hin[rowBase+row] @ W_e )  (W: [., HDIM, DIM])
__global__ void __launch_bounds__(256, 2)
gemm_down_kernel(const float* __restrict__ Hin, const float* __restrict__ W,
                 float* __restrict__ Out, int routed) {
    int e = blockIdx.z;
    int rows, rowBase;
    if (routed) { rows = g_counts[e]; rowBase = g_offsets[e]; }
    else        { rows = NTOK;        rowBase = 0; }
    int rowTile = blockIdx.y * 128;
    if (rowTile >= rows) return;
    int colTile = blockIdx.x * 128;
    const float* Wp = W + (size_t)e * HDIM * DIM;

    __shared__ float As[16][128];
    __shared__ float Bs[16][128];

    int tid = threadIdx.x;
    int tr = tid >> 4, tc = tid & 15;
    int ar0 = tid >> 2;
    int ak  = (tid & 3) * 4;
    int gr0 = rowTile + ar0, gr1 = rowTile + ar0 + 64;
    bool v0 = gr0 < rows, v1 = gr1 < rows;
    int bk0 = tid >> 5;
    int bn  = (tid & 31) * 4;

    float acc[8][8];
#pragma unroll
    for (int i = 0; i < 8; i++)
#pragma unroll
        for (int j = 0; j < 8; j++) acc[i][j] = 0.f;

    for (int k0 = 0; k0 < HDIM; k0 += 16) {
        float4 a0 = make_float4(0.f, 0.f, 0.f, 0.f), a1 = a0;
        if (v0) a0 = *(const float4*)(Hin + (size_t)(rowBase + gr0) * HDIM + k0 + ak);
        if (v1) a1 = *(const float4*)(Hin + (size_t)(rowBase + gr1) * HDIM + k0 + ak);
        const float* Bp = Wp + (size_t)(k0 + bk0) * DIM + colTile + bn;
        float4 b0 = *(const float4*)Bp;
        float4 b1 = *(const float4*)(Bp + (size_t)8 * DIM);
        __syncthreads();
        As[ak + 0][ar0] = a0.x; As[ak + 1][ar0] = a0.y;
        As[ak + 2][ar0] = a0.z; As[ak + 3][ar0] = a0.w;
        As[ak + 0][ar0 + 64] = a1.x; As[ak + 1][ar0 + 64] = a1.y;
        As[ak + 2][ar0 + 64] = a1.z; As[ak + 3][ar0 + 64] = a1.w;
        *(float4*)&Bs[bk0][bn]     = b0;
        *(float4*)&Bs[bk0 + 8][bn] = b1;
        __syncthreads();
#pragma unroll
        for (int kk = 0; kk < 16; kk++) {
            float ra[8], rb[8];
            *(float4*)&ra[0] = *(const float4*)&As[kk][tr * 8];
            *(float4*)&ra[4] = *(const float4*)&As[kk][tr * 8 + 4];
            *(float4*)&rb[0] = *(const float4*)&Bs[kk][tc * 8];
            *(float4*)&rb[4] = *(const float4*)&Bs[kk][tc * 8 + 4];
#pragma unroll
            for (int i = 0; i < 8; i++)
#pragma unroll
                for (int j = 0; j < 8; j++) acc[i][j] += ra[i] * rb[j];
        }
    }
#pragma unroll
    for (int i = 0; i < 8; i++) {
        int gr = rowTile + tr * 8 + i;
        if (gr < rows) {
            float scale = routed ? g_pair_prob[rowBase + gr] : 1.f;
            float* o = Out + (size_t)(rowBase + gr) * DIM + colTile + tc * 8;
            float v[8];
#pragma unroll
            for (int j = 0; j < 8; j++) v[j] = acc[i][j] * scale;
            *(float4*)&o[0] = *(float4*)&v[0];
            *(float4*)&o[4] = *(float4*)&v[4];
        }
    }
}

// out[token] += pair_out[pos0] + pair_out[pos1]   (deterministic slot order)
__global__ void combine_kernel(float* __restrict__ out) {
    int n = blockIdx.x;
    int d = threadIdx.x * 4;
    int p0 = g_pair_pos[2 * n];
    int p1 = g_pair_pos[2 * n + 1];
    float4 o  = *(float4*)(out + (size_t)n * DIM + d);
    float4 a  = *(const float4*)(g_pair_out + (size_t)p0 * DIM + d);
    float4 b  = *(const float4*)(g_pair_out + (size_t)p1 * DIM + d);
    o.x += a.x + b.x; o.y += a.y + b.y; o.z += a.z + b.z; o.w += a.w + b.w;
    *(float4*)(out + (size_t)n * DIM + d) = o;
}

// ---------------- launch -----------------------------------------------------
extern "C" void kernel_launch(void* const* d_in, const int* in_sizes, int n_in,
                              void* d_out, int out_size) {
    const float* x   = (const float*)d_in[0];
    const float* Wr  = (const float*)d_in[1];
    const float* Wup = (const float*)d_in[2];
    const float* Wdn = (const float*)d_in[3];
    const float* Wsu = (const float*)d_in[4];
    const float* Wsd = (const float*)d_in[5];
    float* out = (float*)d_out;

    void *p_h_sh = nullptr, *p_h_rt = nullptr, *p_pair_out = nullptr;
    cudaGetSymbolAddress(&p_h_sh, g_h_sh);
    cudaGetSymbolAddress(&p_h_rt, g_h_rt);
    cudaGetSymbolAddress(&p_pair_out, g_pair_out);
    float* h_sh = (float*)p_h_sh;
    float* h_rt = (float*)p_h_rt;
    float* pair_out = (float*)p_pair_out;

    zero_counts_kernel<<<1, 32>>>();
    router_kernel<<<NTOK / 4, 128>>>(x, Wr);
    prefix_kernel<<<1, 32>>>();
    scatter_kernel<<<NTOK / 256, 256>>>();

    // shared expert
    {
        dim3 g(HDIM / 128, NTOK / 128, 1);
        gemm_up_kernel<<<g, 256>>>(x, Wsu, h_sh, 0);
    }
    {
        dim3 g(DIM / 128, NTOK / 128, 1);
        gemm_down_kernel<<<g, 256>>>(h_sh, Wsd, out, 0);
    }
    // routed experts (grouped, compact permutation)
    {
        dim3 g(HDIM / 128, NTOK / 128, NEXP);
        gemm_up_kernel<<<g, 256>>>(x, Wup, h_rt, 1);
    }
    {
        dim3 g(DIM / 128, NTOK / 128, NEXP);
        gemm_down_kernel<<<g, 256>>>(h_rt, Wdn, pair_out, 1);
    }
    combine_kernel<<<NTOK, 256>>>(out);
}

// round 10
// speedup vs baseline: 2.8698x; 2.8698x over previous
#include <cuda_runtime.h>
#include <cuda_bf16.h>
#include <math.h>
#include <stdint.h>

#define NTOK 4096
#define DIM  1024
#define HDIM 4096
#define NEXP 8
#define NPAIR (NTOK * 2)

#define BM 128
#define BN 128
#define BK 64
#define STAGES 3
#define TILE_B 16384            // 128 rows x 128 bytes (64 bf16)
#define STAGE_B (4 * TILE_B)    // Ah, Al, Bh, Bl
#define GEMM_SMEM (STAGES * STAGE_B)

// ---------------- scratch (static device globals; no runtime allocation) ----
__device__ __nv_bfloat16 g_x_hi[(size_t)NTOK * DIM];
__device__ __nv_bfloat16 g_x_lo[(size_t)NTOK * DIM];
__device__ __nv_bfloat16 g_xg_hi[(size_t)NPAIR * DIM];
__device__ __nv_bfloat16 g_xg_lo[(size_t)NPAIR * DIM];
__device__ __nv_bfloat16 g_wupT_hi[(size_t)NEXP * HDIM * DIM];  // [e][h][d]
__device__ __nv_bfloat16 g_wupT_lo[(size_t)NEXP * HDIM * DIM];
__device__ __nv_bfloat16 g_wdnT_hi[(size_t)NEXP * DIM * HDIM];  // [e][d][h]
__device__ __nv_bfloat16 g_wdnT_lo[(size_t)NEXP * DIM * HDIM];
__device__ __nv_bfloat16 g_wsuT_hi[(size_t)HDIM * DIM];
__device__ __nv_bfloat16 g_wsuT_lo[(size_t)HDIM * DIM];
__device__ __nv_bfloat16 g_wsdT_hi[(size_t)DIM * HDIM];
__device__ __nv_bfloat16 g_wsdT_lo[(size_t)DIM * HDIM];
__device__ __nv_bfloat16 g_hsh_hi[(size_t)NTOK * HDIM];
__device__ __nv_bfloat16 g_hsh_lo[(size_t)NTOK * HDIM];
__device__ __nv_bfloat16 g_hrt_hi[(size_t)NPAIR * HDIM];
__device__ __nv_bfloat16 g_hrt_lo[(size_t)NPAIR * HDIM];
__device__ float g_pair_out[(size_t)NPAIR * DIM];
__device__ float g_pair_prob[NPAIR];
__device__ int   g_pair_token[NPAIR];
__device__ int   g_pair_pos[NPAIR];
__device__ int   g_topk_idx[NPAIR];
__device__ float g_topk_p[NPAIR];
__device__ int   g_counts[NEXP];
__device__ int   g_offsets[NEXP];
__device__ int   g_cursor[NEXP];

// ---------------- PTX helpers (sm_80-era only: valid on plain sm_103) -------
__device__ __forceinline__ uint32_t smem_u32(const void* p) {
    return (uint32_t)__cvta_generic_to_shared(p);
}
#define CP_ASYNC(dst, src, sz) \
    asm volatile("cp.async.cg.shared.global [%0], [%1], 16, %2;" \
                 :: "r"(dst), "l"(src), "r"(sz) : "memory")
#define CP_COMMIT() asm volatile("cp.async.commit_group;" ::: "memory")
#define CP_WAIT(n)  asm volatile("cp.async.wait_group %0;" :: "n"(n) : "memory")
#define LDSM4(r, a) \
    asm volatile("ldmatrix.sync.aligned.m8n8.x4.shared.b16 {%0,%1,%2,%3}, [%4];" \
                 : "=r"((r)[0]), "=r"((r)[1]), "=r"((r)[2]), "=r"((r)[3]) : "r"(a))
#define MMA16816(c, a, b0, b1) \
    asm volatile("mma.sync.aligned.m16n8k16.row.col.f32.bf16.bf16.f32 " \
                 "{%0,%1,%2,%3},{%4,%5,%6,%7},{%8,%9},{%0,%1,%2,%3};" \
                 : "+f"((c)[0]), "+f"((c)[1]), "+f"((c)[2]), "+f"((c)[3]) \
                 : "r"((a)[0]), "r"((a)[1]), "r"((a)[2]), "r"((a)[3]), \
                   "r"(b0), "r"(b1))

// ---------------- tiny kernels ----------------------------------------------
__global__ void zero_counts_kernel() {
    if (threadIdx.x < NEXP) g_counts[threadIdx.x] = 0;
}

__global__ void router_kernel(const float* __restrict__ x,
                              const float* __restrict__ Wr) {
    int gw   = (blockIdx.x * blockDim.x + threadIdx.x) >> 5;
    int lane = threadIdx.x & 31;
    if (gw >= NTOK) return;
    const float* xr = x + (size_t)gw * DIM;
    float acc[NEXP];
#pragma unroll
    for (int e = 0; e < NEXP; e++) acc[e] = 0.f;
    for (int d = lane; d < DIM; d += 32) {
        float xv = xr[d];
        const float* w = Wr + (size_t)d * NEXP;
#pragma unroll
        for (int e = 0; e < NEXP; e++) acc[e] += xv * w[e];
    }
#pragma unroll
    for (int off = 16; off > 0; off >>= 1) {
#pragma unroll
        for (int e = 0; e < NEXP; e++)
            acc[e] += __shfl_xor_sync(0xffffffffu, acc[e], off);
    }
    if (lane == 0) {
        float p[NEXP];
#pragma unroll
        for (int e = 0; e < NEXP; e++) p[e] = 1.f / (1.f + expf(-acc[e]));
        float p1 = -1.f, p2 = -1.f; int i1 = 0, i2 = 0;
#pragma unroll
        for (int e = 0; e < NEXP; e++) {
            float v = p[e];
            if (v > p1)      { p2 = p1; i2 = i1; p1 = v; i1 = e; }
            else if (v > p2) { p2 = v;  i2 = e; }
        }
        float s = p1 + p2 + 1e-6f;
        p1 /= s; p2 /= s;
        g_topk_idx[2 * gw]     = i1;  g_topk_idx[2 * gw + 1] = i2;
        g_topk_p[2 * gw]       = p1;  g_topk_p[2 * gw + 1]   = p2;
        atomicAdd(&g_counts[i1], 1);
        atomicAdd(&g_counts[i2], 1);
    }
}

__global__ void prefix_kernel() {
    if (threadIdx.x == 0) {
        int s = 0;
        for (int e = 0; e < NEXP; e++) {
            g_offsets[e] = s; g_cursor[e] = s; s += g_counts[e];
        }
    }
}

__global__ void scatter_kernel() {
    int n = blockIdx.x * blockDim.x + threadIdx.x;
    if (n >= NTOK) return;
#pragma unroll
    for (int j = 0; j < 2; j++) {
        int e = g_topk_idx[2 * n + j];
        int pos = atomicAdd(&g_cursor[e], 1);
        g_pair_token[pos] = n;
        g_pair_prob[pos]  = g_topk_p[2 * n + j];
        g_pair_pos[2 * n + j] = pos;
    }
}

__global__ void split_x_kernel(const float* __restrict__ x) {
    size_t i = ((size_t)blockIdx.x * blockDim.x + threadIdx.x) * 4;
    float4 v = *(const float4*)(x + i);
    float f[4] = {v.x, v.y, v.z, v.w};
    uint32_t hi[2], lo[2];
#pragma unroll
    for (int p = 0; p < 2; p++) {
        __nv_bfloat16 h0 = __float2bfloat16(f[2 * p]);
        __nv_bfloat16 h1 = __float2bfloat16(f[2 * p + 1]);
        __nv_bfloat16 l0 = __float2bfloat16(f[2 * p] - __bfloat162float(h0));
        __nv_bfloat16 l1 = __float2bfloat16(f[2 * p + 1] - __bfloat162float(h1));
        hi[p] = (uint32_t)__bfloat16_as_ushort(h0) | ((uint32_t)__bfloat16_as_ushort(h1) << 16);
        lo[p] = (uint32_t)__bfloat16_as_ushort(l0) | ((uint32_t)__bfloat16_as_ushort(l1) << 16);
    }
    *(uint2*)(g_x_hi + i) = make_uint2(hi[0], hi[1]);
    *(uint2*)(g_x_lo + i) = make_uint2(lo[0], lo[1]);
}

__global__ void gather_x_kernel() {
    int pos = blockIdx.x;
    int tok = g_pair_token[pos];
    int d = threadIdx.x;  // 128 threads x 8 bf16
    ((uint4*)(g_xg_hi + (size_t)pos * DIM))[d] =
        ((const uint4*)(g_x_hi + (size_t)tok * DIM))[d];
    ((uint4*)(g_xg_lo + (size_t)pos * DIM))[d] =
        ((const uint4*)(g_x_lo + (size_t)tok * DIM))[d];
}

// transpose [R,C] fp32 -> [C,R] bf16 hi/lo  (blockIdx.z = expert slab)
__global__ void transpose_split_kernel(const float* __restrict__ src,
                                       __nv_bfloat16* __restrict__ dhi,
                                       __nv_bfloat16* __restrict__ dlo,
                                       int R, int C) {
    __shared__ float tile[32][33];
    size_t eo = (size_t)blockIdx.z * R * C;
    int c0 = blockIdx.x * 32, r0 = blockIdx.y * 32;
    int tx = threadIdx.x, ty = threadIdx.y;
#pragma unroll
    for (int i = 0; i < 4; i++)
        tile[ty + 8 * i][tx] = src[eo + (size_t)(r0 + ty + 8 * i) * C + c0 + tx];
    __syncthreads();
#pragma unroll
    for (int i = 0; i < 4; i++) {
        float v = tile[tx][ty + 8 * i];
        __nv_bfloat16 h = __float2bfloat16(v);
        __nv_bfloat16 l = __float2bfloat16(v - __bfloat162float(h));
        size_t o = eo + (size_t)(c0 + ty + 8 * i) * R + r0 + tx;
        dhi[o] = h; dlo[o] = l;
    }
}

// ---------------- HMMA bf16x3 GEMM ------------------------------------------
// C[128m,128n] = A@B^T. A,B K-major bf16 hi/lo; cp.async 3-stage pipeline;
// XOR-swizzled smem (16B chunk ^= row&7 within 128B rows), ldmatrix fragments,
// mma.m16n8k16 x3 products -> fp32-class accuracy.

__device__ __forceinline__ void load_stage(uint32_t sbase,
    const char* Ah, const char* Al, const char* Bh, const char* Bl,
    size_t rowB, size_t kb, int rmax, int tid) {
#pragma unroll
    for (int t = 0; t < 4; t++) {
        int id = tid + t * 256;
        int r = id >> 3, c = id & 7;
        uint32_t dst = sbase + (uint32_t)(r * 128 + ((c ^ (r & 7)) << 4));
        size_t go = (size_t)r * rowB + kb + (size_t)(c << 4);
        int av = (r < rmax);
        size_t ga = av ? go : 0;
        int sz = av ? 16 : 0;
        CP_ASYNC(dst,              Ah + ga, sz);
        CP_ASYNC(dst + TILE_B,     Al + ga, sz);
        CP_ASYNC(dst + 2 * TILE_B, Bh + go, 16);
        CP_ASYNC(dst + 3 * TILE_B, Bl + go, 16);
    }
}

template <int OP>  // 0 = up (sq_relu -> bf16 hi/lo), 1 = down (scale -> fp32)
__global__ void __launch_bounds__(256, 1)
gemm_mma(const __nv_bfloat16* __restrict__ Ahi, const __nv_bfloat16* __restrict__ Alo,
         const __nv_bfloat16* __restrict__ Bhi, const __nv_bfloat16* __restrict__ Blo,
         __nv_bfloat16* __restrict__ Ohi, __nv_bfloat16* __restrict__ Olo,
         float* __restrict__ Out, int Klen, int Nlen, int routed) {
    int e = blockIdx.z;
    int rows    = routed ? g_counts[e]  : NTOK;
    int rowBase = routed ? g_offsets[e] : 0;
    int rowTile = blockIdx.y * BM;
    if (rowTile >= rows) return;
    int colTile = blockIdx.x * BN;
    extern __shared__ char smem[];
    uint32_t sb = smem_u32(smem);
    int tid = threadIdx.x, wid = tid >> 5, lane = tid & 31;
    int rmax = rows - rowTile;

    const char* Ah = (const char*)(Ahi + (size_t)(rowBase + rowTile) * Klen);
    const char* Al = (const char*)(Alo + (size_t)(rowBase + rowTile) * Klen);
    const char* Bh = (const char*)(Bhi + ((size_t)e * Nlen + colTile) * Klen);
    const char* Bl = (const char*)(Blo + ((size_t)e * Nlen + colTile) * Klen);
    size_t rowB = (size_t)Klen * 2;
    int nCh = Klen >> 6;

    // prologue: stages 0,1
    load_stage(sb,           Ah, Al, Bh, Bl, rowB, 0,   rmax, tid); CP_COMMIT();
    load_stage(sb + STAGE_B, Ah, Al, Bh, Bl, rowB, 128, rmax, tid); CP_COMMIT();

    int wm = (wid >> 1) << 5;  // warp m offset (4 warps x 32 rows)
    int wn = (wid & 1) << 6;   // warp n offset (2 warps x 64 cols)

    float acc[2][8][4];
#pragma unroll
    for (int a = 0; a < 2; a++)
#pragma unroll
        for (int b = 0; b < 8; b++)
#pragma unroll
            for (int c = 0; c < 4; c++) acc[a][b][c] = 0.f;

    for (int i = 0; i < nCh; i++) {
        CP_WAIT(1);
        __syncthreads();
        int nx = i + STAGES - 1;
        if (nx < nCh)
            load_stage(sb + (uint32_t)(nx % STAGES) * STAGE_B,
                       Ah, Al, Bh, Bl, rowB, (size_t)nx * 128, rmax, tid);
        CP_COMMIT();

        uint32_t st = sb + (uint32_t)(i % STAGES) * STAGE_B;
#pragma unroll
        for (int ks = 0; ks < 4; ks++) {
            uint32_t ah[2][4], al[2][4];
#pragma unroll
            for (int mt = 0; mt < 2; mt++) {
                int row = wm + (mt << 4) + (lane & 15);
                int ch  = (ks << 1) + (lane >> 4);
                uint32_t a = st + (uint32_t)(row * 128 + ((ch ^ (row & 7)) << 4));
                LDSM4(ah[mt], a);
                LDSM4(al[mt], a + TILE_B);
            }
            uint32_t bh[4][4], bl[4][4];
#pragma unroll
            for (int g = 0; g < 4; g++) {
                int n  = wn + (g << 4) + ((lane >> 4) << 3) + (lane & 7);
                int ch = (ks << 1) + ((lane >> 3) & 1);
                uint32_t a = st + 2 * TILE_B + (uint32_t)(n * 128 + ((ch ^ (n & 7)) << 4));
                LDSM4(bh[g], a);
                LDSM4(bl[g], a + TILE_B);
            }
#pragma unroll
            for (int mt = 0; mt < 2; mt++)
#pragma unroll
                for (int nt = 0; nt < 8; nt++) {
                    int g = nt >> 1, i0 = (nt & 1) << 1;
                    MMA16816(acc[mt][nt], ah[mt], bh[g][i0], bh[g][i0 + 1]);
                    MMA16816(acc[mt][nt], ah[mt], bl[g][i0], bl[g][i0 + 1]);
                    MMA16816(acc[mt][nt], al[mt], bh[g][i0], bh[g][i0 + 1]);
                }
        }
    }

    // epilogue: c0/c1 -> (row=lane>>2, col=(lane&3)*2, +1); c2/c3 -> row+8
#pragma unroll
    for (int mt = 0; mt < 2; mt++) {
#pragma unroll
        for (int half = 0; half < 2; half++) {
            int r = wm + (mt << 4) + (lane >> 2) + (half << 3);
            if (r < rmax) {
                size_t grow = (size_t)(rowBase + rowTile + r) * Nlen + colTile + wn;
                if (OP == 0) {
#pragma unroll
                    for (int nt = 0; nt < 8; nt++) {
                        float f0 = acc[mt][nt][half * 2];
                        float f1 = acc[mt][nt][half * 2 + 1];
                        f0 = fmaxf(f0, 0.f); f0 *= f0;
                        f1 = fmaxf(f1, 0.f); f1 *= f1;
                        __nv_bfloat16 h0 = __float2bfloat16(f0);
                        __nv_bfloat16 h1 = __float2bfloat16(f1);
                        __nv_bfloat16 l0 = __float2bfloat16(f0 - __bfloat162float(h0));
                        __nv_bfloat16 l1 = __float2bfloat16(f1 - __bfloat162float(h1));
                        int col = (nt << 3) + ((lane & 3) << 1);
                        *(uint32_t*)(Ohi + grow + col) =
                            (uint32_t)__bfloat16_as_ushort(h0) |
                            ((uint32_t)__bfloat16_as_ushort(h1) << 16);
                        *(uint32_t*)(Olo + grow + col) =
                            (uint32_t)__bfloat16_as_ushort(l0) |
                            ((uint32_t)__bfloat16_as_ushort(l1) << 16);
                    }
                } else {
                    float scale = routed ? g_pair_prob[rowBase + rowTile + r] : 1.f;
#pragma unroll
                    for (int nt = 0; nt < 8; nt++) {
                        int col = (nt << 3) + ((lane & 3) << 1);
                        float2 v;
                        v.x = acc[mt][nt][half * 2]     * scale;
                        v.y = acc[mt][nt][half * 2 + 1] * scale;
                        *(float2*)(Out + grow + col) = v;
                    }
                }
            }
        }
    }
}

// out[token] += pair_out[pos0] + pair_out[pos1]
__global__ void combine_kernel(float* __restrict__ out) {
    int n = blockIdx.x;
    int d = threadIdx.x * 4;
    int p0 = g_pair_pos[2 * n];
    int p1 = g_pair_pos[2 * n + 1];
    float4 o = *(float4*)(out + (size_t)n * DIM + d);
    float4 a = *(const float4*)(g_pair_out + (size_t)p0 * DIM + d);
    float4 b = *(const float4*)(g_pair_out + (size_t)p1 * DIM + d);
    o.x += a.x + b.x; o.y += a.y + b.y; o.z += a.z + b.z; o.w += a.w + b.w;
    *(float4*)(out + (size_t)n * DIM + d) = o;
}

// ---------------- launch -----------------------------------------------------
extern "C" void kernel_launch(void* const* d_in, const int* in_sizes, int n_in,
                              void* d_out, int out_size) {
    const float* x   = (const float*)d_in[0];
    const float* Wr  = (const float*)d_in[1];
    const float* Wup = (const float*)d_in[2];
    const float* Wdn = (const float*)d_in[3];
    const float* Wsu = (const float*)d_in[4];
    const float* Wsd = (const float*)d_in[5];
    float* out = (float*)d_out;

    cudaFuncSetAttribute(gemm_mma<0>, cudaFuncAttributeMaxDynamicSharedMemorySize, GEMM_SMEM);
    cudaFuncSetAttribute(gemm_mma<1>, cudaFuncAttributeMaxDynamicSharedMemorySize, GEMM_SMEM);

    void* p;
    cudaGetSymbolAddress(&p, g_x_hi);    __nv_bfloat16* x_hi    = (__nv_bfloat16*)p;
    cudaGetSymbolAddress(&p, g_x_lo);    __nv_bfloat16* x_lo    = (__nv_bfloat16*)p;
    cudaGetSymbolAddress(&p, g_xg_hi);   __nv_bfloat16* xg_hi   = (__nv_bfloat16*)p;
    cudaGetSymbolAddress(&p, g_xg_lo);   __nv_bfloat16* xg_lo   = (__nv_bfloat16*)p;
    cudaGetSymbolAddress(&p, g_wupT_hi); __nv_bfloat16* wupT_hi = (__nv_bfloat16*)p;
    cudaGetSymbolAddress(&p, g_wupT_lo); __nv_bfloat16* wupT_lo = (__nv_bfloat16*)p;
    cudaGetSymbolAddress(&p, g_wdnT_hi); __nv_bfloat16* wdnT_hi = (__nv_bfloat16*)p;
    cudaGetSymbolAddress(&p, g_wdnT_lo); __nv_bfloat16* wdnT_lo = (__nv_bfloat16*)p;
    cudaGetSymbolAddress(&p, g_wsuT_hi); __nv_bfloat16* wsuT_hi = (__nv_bfloat16*)p;
    cudaGetSymbolAddress(&p, g_wsuT_lo); __nv_bfloat16* wsuT_lo = (__nv_bfloat16*)p;
    cudaGetSymbolAddress(&p, g_wsdT_hi); __nv_bfloat16* wsdT_hi = (__nv_bfloat16*)p;
    cudaGetSymbolAddress(&p, g_wsdT_lo); __nv_bfloat16* wsdT_lo = (__nv_bfloat16*)p;
    cudaGetSymbolAddress(&p, g_hsh_hi);  __nv_bfloat16* hsh_hi  = (__nv_bfloat16*)p;
    cudaGetSymbolAddress(&p, g_hsh_lo);  __nv_bfloat16* hsh_lo  = (__nv_bfloat16*)p;
    cudaGetSymbolAddress(&p, g_hrt_hi);  __nv_bfloat16* hrt_hi  = (__nv_bfloat16*)p;
    cudaGetSymbolAddress(&p, g_hrt_lo);  __nv_bfloat16* hrt_lo  = (__nv_bfloat16*)p;
    cudaGetSymbolAddress(&p, g_pair_out); float* pair_out = (float*)p;

    // routing
    zero_counts_kernel<<<1, 32>>>();
    router_kernel<<<NTOK / 4, 128>>>(x, Wr);
    prefix_kernel<<<1, 32>>>();
    scatter_kernel<<<NTOK / 256, 256>>>();

    // operand prep
    split_x_kernel<<<(NTOK * DIM) / (256 * 4), 256>>>(x);
    gather_x_kernel<<<NPAIR, 128>>>();
    {
        dim3 t(32, 8, 1);
        transpose_split_kernel<<<dim3(HDIM / 32, DIM / 32, NEXP), t>>>(Wup, wupT_hi, wupT_lo, DIM, HDIM);
        transpose_split_kernel<<<dim3(DIM / 32, HDIM / 32, NEXP), t>>>(Wdn, wdnT_hi, wdnT_lo, HDIM, DIM);
        transpose_split_kernel<<<dim3(HDIM / 32, DIM / 32, 1), t>>>(Wsu, wsuT_hi, wsuT_lo, DIM, HDIM);
        transpose_split_kernel<<<dim3(DIM / 32, HDIM / 32, 1), t>>>(Wsd, wsdT_hi, wsdT_lo, HDIM, DIM);
    }

    // shared expert
    gemm_mma<0><<<dim3(HDIM / BN, NTOK / BM, 1), 256, GEMM_SMEM>>>(
        x_hi, x_lo, wsuT_hi, wsuT_lo, hsh_hi, hsh_lo, nullptr, DIM, HDIM, 0);
    gemm_mma<1><<<dim3(DIM / BN, NTOK / BM, 1), 256, GEMM_SMEM>>>(
        hsh_hi, hsh_lo, wsdT_hi, wsdT_lo, nullptr, nullptr, out, HDIM, DIM, 0);

    // routed experts (compact pair ordering; grid.y covers worst-case NPAIR rows)
    gemm_mma<0><<<dim3(HDIM / BN, NPAIR / BM, NEXP), 256, GEMM_SMEM>>>(
        xg_hi, xg_lo, wupT_hi, wupT_lo, hrt_hi, hrt_lo, nullptr, DIM, HDIM, 1);
    gemm_mma<1><<<dim3(DIM / BN, NPAIR / BM, NEXP), 256, GEMM_SMEM>>>(
        hrt_hi, hrt_lo, wdnT_hi, wdnT_lo, nullptr, nullptr, pair_out, HDIM, DIM, 1);

    combine_kernel<<<NTOK, 256>>>(out);
}

// round 11
// speedup vs baseline: 2.8720x; 1.0007x over previous
#include <cuda_runtime.h>
#include <cuda_bf16.h>
#include <math.h>
#include <stdint.h>

#define NTOK 4096
#define DIM  1024
#define HDIM 4096
#define NEXP 8
#define NPAIR (NTOK * 2)

#define BM 128
#define BN 128
#define BK 64
#define STAGES 3
#define TILE_B 16384            // 128 rows x 128 bytes (64 bf16)
#define STAGE_B (4 * TILE_B)    // Ah, Al, Bh, Bl
#define GEMM_SMEM (STAGES * STAGE_B)

// ---------------- scratch (static device globals; no runtime allocation) ----
__device__ __nv_bfloat16 g_x_hi[(size_t)NTOK * DIM];
__device__ __nv_bfloat16 g_x_lo[(size_t)NTOK * DIM];
__device__ __nv_bfloat16 g_xg_hi[(size_t)NPAIR * DIM];
__device__ __nv_bfloat16 g_xg_lo[(size_t)NPAIR * DIM];
__device__ __nv_bfloat16 g_wupT_hi[(size_t)NEXP * HDIM * DIM];  // [e][h][d]
__device__ __nv_bfloat16 g_wupT_lo[(size_t)NEXP * HDIM * DIM];
__device__ __nv_bfloat16 g_wdnT_hi[(size_t)NEXP * DIM * HDIM];  // [e][d][h]
__device__ __nv_bfloat16 g_wdnT_lo[(size_t)NEXP * DIM * HDIM];
__device__ __nv_bfloat16 g_wsuT_hi[(size_t)HDIM * DIM];
__device__ __nv_bfloat16 g_wsuT_lo[(size_t)HDIM * DIM];
__device__ __nv_bfloat16 g_wsdT_hi[(size_t)DIM * HDIM];
__device__ __nv_bfloat16 g_wsdT_lo[(size_t)DIM * HDIM];
__device__ __nv_bfloat16 g_hsh_hi[(size_t)NTOK * HDIM];
__device__ __nv_bfloat16 g_hsh_lo[(size_t)NTOK * HDIM];
__device__ __nv_bfloat16 g_hrt_hi[(size_t)NPAIR * HDIM];
__device__ __nv_bfloat16 g_hrt_lo[(size_t)NPAIR * HDIM];
__device__ float g_pair_out[(size_t)NPAIR * DIM];
__device__ float g_pair_prob[NPAIR];
__device__ int   g_pair_token[NPAIR];
__device__ int   g_pair_pos[NPAIR];
__device__ int   g_topk_idx[NPAIR];
__device__ float g_topk_p[NPAIR];
__device__ int   g_counts[NEXP];
__device__ int   g_offsets[NEXP];
__device__ int   g_cursor[NEXP];

// ---------------- PTX helpers (sm_80-era only: valid on plain sm_103) -------
__device__ __forceinline__ uint32_t smem_u32(const void* p) {
    return (uint32_t)__cvta_generic_to_shared(p);
}
#define CP_ASYNC(dst, src, sz) \
    asm volatile("cp.async.cg.shared.global [%0], [%1], 16, %2;" \
                 :: "r"(dst), "l"(src), "r"(sz) : "memory")
#define CP_COMMIT() asm volatile("cp.async.commit_group;" ::: "memory")
#define CP_WAIT(n)  asm volatile("cp.async.wait_group %0;" :: "n"(n) : "memory")
#define LDSM4(r, a) \
    asm volatile("ldmatrix.sync.aligned.m8n8.x4.shared.b16 {%0,%1,%2,%3}, [%4];" \
                 : "=r"((r)[0]), "=r"((r)[1]), "=r"((r)[2]), "=r"((r)[3]) : "r"(a))
#define MMA16816(c, a, b0, b1) \
    asm volatile("mma.sync.aligned.m16n8k16.row.col.f32.bf16.bf16.f32 " \
                 "{%0,%1,%2,%3},{%4,%5,%6,%7},{%8,%9},{%0,%1,%2,%3};" \
                 : "+f"((c)[0]), "+f"((c)[1]), "+f"((c)[2]), "+f"((c)[3]) \
                 : "r"((a)[0]), "r"((a)[1]), "r"((a)[2]), "r"((a)[3]), \
                   "r"(b0), "r"(b1))

// ---------------- tiny kernels ----------------------------------------------
__global__ void zero_counts_kernel() {
    if (threadIdx.x < NEXP) g_counts[threadIdx.x] = 0;
}

__global__ void router_kernel(const float* __restrict__ x,
                              const float* __restrict__ Wr) {
    int gw   = (blockIdx.x * blockDim.x + threadIdx.x) >> 5;
    int lane = threadIdx.x & 31;
    if (gw >= NTOK) return;
    const float* xr = x + (size_t)gw * DIM;
    float acc[NEXP];
#pragma unroll
    for (int e = 0; e < NEXP; e++) acc[e] = 0.f;
    for (int d = lane; d < DIM; d += 32) {
        float xv = xr[d];
        const float* w = Wr + (size_t)d * NEXP;
#pragma unroll
        for (int e = 0; e < NEXP; e++) acc[e] += xv * w[e];
    }
#pragma unroll
    for (int off = 16; off > 0; off >>= 1) {
#pragma unroll
        for (int e = 0; e < NEXP; e++)
            acc[e] += __shfl_xor_sync(0xffffffffu, acc[e], off);
    }
    if (lane == 0) {
        float p[NEXP];
#pragma unroll
        for (int e = 0; e < NEXP; e++) p[e] = 1.f / (1.f + expf(-acc[e]));
        float p1 = -1.f, p2 = -1.f; int i1 = 0, i2 = 0;
#pragma unroll
        for (int e = 0; e < NEXP; e++) {
            float v = p[e];
            if (v > p1)      { p2 = p1; i2 = i1; p1 = v; i1 = e; }
            else if (v > p2) { p2 = v;  i2 = e; }
        }
        float s = p1 + p2 + 1e-6f;
        p1 /= s; p2 /= s;
        g_topk_idx[2 * gw]     = i1;  g_topk_idx[2 * gw + 1] = i2;
        g_topk_p[2 * gw]       = p1;  g_topk_p[2 * gw + 1]   = p2;
        atomicAdd(&g_counts[i1], 1);
        atomicAdd(&g_counts[i2], 1);
    }
}

__global__ void prefix_kernel() {
    if (threadIdx.x == 0) {
        int s = 0;
        for (int e = 0; e < NEXP; e++) {
            g_offsets[e] = s; g_cursor[e] = s; s += g_counts[e];
        }
    }
}

__global__ void scatter_kernel() {
    int n = blockIdx.x * blockDim.x + threadIdx.x;
    if (n >= NTOK) return;
#pragma unroll
    for (int j = 0; j < 2; j++) {
        int e = g_topk_idx[2 * n + j];
        int pos = atomicAdd(&g_cursor[e], 1);
        g_pair_token[pos] = n;
        g_pair_prob[pos]  = g_topk_p[2 * n + j];
        g_pair_pos[2 * n + j] = pos;
    }
}

__global__ void split_x_kernel(const float* __restrict__ x) {
    size_t i = ((size_t)blockIdx.x * blockDim.x + threadIdx.x) * 4;
    float4 v = *(const float4*)(x + i);
    float f[4] = {v.x, v.y, v.z, v.w};
    uint32_t hi[2], lo[2];
#pragma unroll
    for (int p = 0; p < 2; p++) {
        __nv_bfloat16 h0 = __float2bfloat16(f[2 * p]);
        __nv_bfloat16 h1 = __float2bfloat16(f[2 * p + 1]);
        __nv_bfloat16 l0 = __float2bfloat16(f[2 * p] - __bfloat162float(h0));
        __nv_bfloat16 l1 = __float2bfloat16(f[2 * p + 1] - __bfloat162float(h1));
        hi[p] = (uint32_t)__bfloat16_as_ushort(h0) | ((uint32_t)__bfloat16_as_ushort(h1) << 16);
        lo[p] = (uint32_t)__bfloat16_as_ushort(l0) | ((uint32_t)__bfloat16_as_ushort(l1) << 16);
    }
    *(uint2*)(g_x_hi + i) = make_uint2(hi[0], hi[1]);
    *(uint2*)(g_x_lo + i) = make_uint2(lo[0], lo[1]);
}

__global__ void gather_x_kernel() {
    int pos = blockIdx.x;
    int tok = g_pair_token[pos];
    int d = threadIdx.x;  // 128 threads x 8 bf16
    ((uint4*)(g_xg_hi + (size_t)pos * DIM))[d] =
        ((const uint4*)(g_x_hi + (size_t)tok * DIM))[d];
    ((uint4*)(g_xg_lo + (size_t)pos * DIM))[d] =
        ((const uint4*)(g_x_lo + (size_t)tok * DIM))[d];
}

// transpose [R,C] fp32 -> [C,R] bf16 hi/lo  (blockIdx.z = expert slab)
__global__ void transpose_split_kernel(const float* __restrict__ src,
                                       __nv_bfloat16* __restrict__ dhi,
                                       __nv_bfloat16* __restrict__ dlo,
                                       int R, int C) {
    __shared__ float tile[32][33];
    size_t eo = (size_t)blockIdx.z * R * C;
    int c0 = blockIdx.x * 32, r0 = blockIdx.y * 32;
    int tx = threadIdx.x, ty = threadIdx.y;
#pragma unroll
    for (int i = 0; i < 4; i++)
        tile[ty + 8 * i][tx] = src[eo + (size_t)(r0 + ty + 8 * i) * C + c0 + tx];
    __syncthreads();
#pragma unroll
    for (int i = 0; i < 4; i++) {
        float v = tile[tx][ty + 8 * i];
        __nv_bfloat16 h = __float2bfloat16(v);
        __nv_bfloat16 l = __float2bfloat16(v - __bfloat162float(h));
        size_t o = eo + (size_t)(c0 + ty + 8 * i) * R + r0 + tx;
        dhi[o] = h; dlo[o] = l;
    }
}

// ---------------- HMMA bf16x3 GEMM ------------------------------------------
// C[128m,128n] = A@B^T. A,B K-major bf16 hi/lo; cp.async 3-stage pipeline;
// XOR-swizzled smem (16B chunk ^= row&7 within 128B rows), ldmatrix fragments,
// mma.m16n8k16 x3 products -> fp32-class accuracy.

__device__ __forceinline__ void load_stage(uint32_t sbase,
    const char* Ah, const char* Al, const char* Bh, const char* Bl,
    size_t rowB, size_t kb, int rmax, int tid) {
#pragma unroll
    for (int t = 0; t < 4; t++) {
        int id = tid + t * 256;
        int r = id >> 3, c = id & 7;
        uint32_t dst = sbase + (uint32_t)(r * 128 + ((c ^ (r & 7)) << 4));
        size_t go = (size_t)r * rowB + kb + (size_t)(c << 4);
        int av = (r < rmax);
        size_t ga = av ? go : 0;
        int sz = av ? 16 : 0;
        CP_ASYNC(dst,              Ah + ga, sz);
        CP_ASYNC(dst + TILE_B,     Al + ga, sz);
        CP_ASYNC(dst + 2 * TILE_B, Bh + go, 16);
        CP_ASYNC(dst + 3 * TILE_B, Bl + go, 16);
    }
}

template <int OP>  // 0 = up (sq_relu -> bf16 hi/lo), 1 = down (scale -> fp32)
__global__ void __launch_bounds__(256, 1)
gemm_mma(const __nv_bfloat16* __restrict__ Ahi, const __nv_bfloat16* __restrict__ Alo,
         const __nv_bfloat16* __restrict__ Bhi, const __nv_bfloat16* __restrict__ Blo,
         __nv_bfloat16* __restrict__ Ohi, __nv_bfloat16* __restrict__ Olo,
         float* __restrict__ Out, int Klen, int Nlen, int routed) {
    int e = blockIdx.z;
    int rows    = routed ? g_counts[e]  : NTOK;
    int rowBase = routed ? g_offsets[e] : 0;
    int rowTile = blockIdx.y * BM;
    if (rowTile >= rows) return;
    int colTile = blockIdx.x * BN;
    extern __shared__ char smem[];
    uint32_t sb = smem_u32(smem);
    int tid = threadIdx.x, wid = tid >> 5, lane = tid & 31;
    int rmax = rows - rowTile;

    const char* Ah = (const char*)(Ahi + (size_t)(rowBase + rowTile) * Klen);
    const char* Al = (const char*)(Alo + (size_t)(rowBase + rowTile) * Klen);
    const char* Bh = (const char*)(Bhi + ((size_t)e * Nlen + colTile) * Klen);
    const char* Bl = (const char*)(Blo + ((size_t)e * Nlen + colTile) * Klen);
    size_t rowB = (size_t)Klen * 2;
    int nCh = Klen >> 6;

    // prologue: stages 0,1
    load_stage(sb,           Ah, Al, Bh, Bl, rowB, 0,   rmax, tid); CP_COMMIT();
    load_stage(sb + STAGE_B, Ah, Al, Bh, Bl, rowB, 128, rmax, tid); CP_COMMIT();

    int wm = (wid >> 1) << 5;  // warp m offset (4 warps x 32 rows)
    int wn = (wid & 1) << 6;   // warp n offset (2 warps x 64 cols)

    float acc[2][8][4];
#pragma unroll
    for (int a = 0; a < 2; a++)
#pragma unroll
        for (int b = 0; b < 8; b++)
#pragma unroll
            for (int c = 0; c < 4; c++) acc[a][b][c] = 0.f;

    for (int i = 0; i < nCh; i++) {
        CP_WAIT(1);
        __syncthreads();
        int nx = i + STAGES - 1;
        if (nx < nCh)
            load_stage(sb + (uint32_t)(nx % STAGES) * STAGE_B,
                       Ah, Al, Bh, Bl, rowB, (size_t)nx * 128, rmax, tid);
        CP_COMMIT();

        uint32_t st = sb + (uint32_t)(i % STAGES) * STAGE_B;
#pragma unroll
        for (int ks = 0; ks < 4; ks++) {
            uint32_t ah[2][4], al[2][4];
#pragma unroll
            for (int mt = 0; mt < 2; mt++) {
                int row = wm + (mt << 4) + (lane & 15);
                int ch  = (ks << 1) + (lane >> 4);
                uint32_t a = st + (uint32_t)(row * 128 + ((ch ^ (row & 7)) << 4));
                LDSM4(ah[mt], a);
                LDSM4(al[mt], a + TILE_B);
            }
            uint32_t bh[4][4], bl[4][4];
#pragma unroll
            for (int g = 0; g < 4; g++) {
                int n  = wn + (g << 4) + ((lane >> 4) << 3) + (lane & 7);
                int ch = (ks << 1) + ((lane >> 3) & 1);
                uint32_t a = st + 2 * TILE_B + (uint32_t)(n * 128 + ((ch ^ (n & 7)) << 4));
                LDSM4(bh[g], a);
                LDSM4(bl[g], a + TILE_B);
            }
#pragma unroll
            for (int mt = 0; mt < 2; mt++)
#pragma unroll
                for (int nt = 0; nt < 8; nt++) {
                    int g = nt >> 1, i0 = (nt & 1) << 1;
                    MMA16816(acc[mt][nt], ah[mt], bh[g][i0], bh[g][i0 + 1]);
                    MMA16816(acc[mt][nt], ah[mt], bl[g][i0], bl[g][i0 + 1]);
                    MMA16816(acc[mt][nt], al[mt], bh[g][i0], bh[g][i0 + 1]);
                }
        }
    }

    // epilogue: c0/c1 -> (row=lane>>2, col=(lane&3)*2, +1); c2/c3 -> row+8
#pragma unroll
    for (int mt = 0; mt < 2; mt++) {
#pragma unroll
        for (int half = 0; half < 2; half++) {
            int r = wm + (mt << 4) + (lane >> 2) + (half << 3);
            if (r < rmax) {
                size_t grow = (size_t)(rowBase + rowTile + r) * Nlen + colTile + wn;
                if (OP == 0) {
#pragma unroll
                    for (int nt = 0; nt < 8; nt++) {
                        float f0 = acc[mt][nt][half * 2];
                        float f1 = acc[mt][nt][half * 2 + 1];
                        f0 = fmaxf(f0, 0.f); f0 *= f0;
                        f1 = fmaxf(f1, 0.f); f1 *= f1;
                        __nv_bfloat16 h0 = __float2bfloat16(f0);
                        __nv_bfloat16 h1 = __float2bfloat16(f1);
                        __nv_bfloat16 l0 = __float2bfloat16(f0 - __bfloat162float(h0));
                        __nv_bfloat16 l1 = __float2bfloat16(f1 - __bfloat162float(h1));
                        int col = (nt << 3) + ((lane & 3) << 1);
                        *(uint32_t*)(Ohi + grow + col) =
                            (uint32_t)__bfloat16_as_ushort(h0) |
                            ((uint32_t)__bfloat16_as_ushort(h1) << 16);
                        *(uint32_t*)(Olo + grow + col) =
                            (uint32_t)__bfloat16_as_ushort(l0) |
                            ((uint32_t)__bfloat16_as_ushort(l1) << 16);
                    }
                } else {
                    float scale = routed ? g_pair_prob[rowBase + rowTile + r] : 1.f;
#pragma unroll
                    for (int nt = 0; nt < 8; nt++) {
                        int col = (nt << 3) + ((lane & 3) << 1);
                        float2 v;
                        v.x = acc[mt][nt][half * 2]     * scale;
                        v.y = acc[mt][nt][half * 2 + 1] * scale;
                        *(float2*)(Out + grow + col) = v;
                    }
                }
            }
        }
    }
}

// out[token] += pair_out[pos0] + pair_out[pos1]
__global__ void combine_kernel(float* __restrict__ out) {
    int n = blockIdx.x;
    int d = threadIdx.x * 4;
    int p0 = g_pair_pos[2 * n];
    int p1 = g_pair_pos[2 * n + 1];
    float4 o = *(float4*)(out + (size_t)n * DIM + d);
    float4 a = *(const float4*)(g_pair_out + (size_t)p0 * DIM + d);
    float4 b = *(const float4*)(g_pair_out + (size_t)p1 * DIM + d);
    o.x += a.x + b.x; o.y += a.y + b.y; o.z += a.z + b.z; o.w += a.w + b.w;
    *(float4*)(out + (size_t)n * DIM + d) = o;
}

// ---------------- launch -----------------------------------------------------
extern "C" void kernel_launch(void* const* d_in, const int* in_sizes, int n_in,
                              void* d_out, int out_size) {
    const float* x   = (const float*)d_in[0];
    const float* Wr  = (const float*)d_in[1];
    const float* Wup = (const float*)d_in[2];
    const float* Wdn = (const float*)d_in[3];
    const float* Wsu = (const float*)d_in[4];
    const float* Wsd = (const float*)d_in[5];
    float* out = (float*)d_out;

    cudaFuncSetAttribute(gemm_mma<0>, cudaFuncAttributeMaxDynamicSharedMemorySize, GEMM_SMEM);
    cudaFuncSetAttribute(gemm_mma<1>, cudaFuncAttributeMaxDynamicSharedMemorySize, GEMM_SMEM);

    void* p;
    cudaGetSymbolAddress(&p, g_x_hi);    __nv_bfloat16* x_hi    = (__nv_bfloat16*)p;
    cudaGetSymbolAddress(&p, g_x_lo);    __nv_bfloat16* x_lo    = (__nv_bfloat16*)p;
    cudaGetSymbolAddress(&p, g_xg_hi);   __nv_bfloat16* xg_hi   = (__nv_bfloat16*)p;
    cudaGetSymbolAddress(&p, g_xg_lo);   __nv_bfloat16* xg_lo   = (__nv_bfloat16*)p;
    cudaGetSymbolAddress(&p, g_wupT_hi); __nv_bfloat16* wupT_hi = (__nv_bfloat16*)p;
    cudaGetSymbolAddress(&p, g_wupT_lo); __nv_bfloat16* wupT_lo = (__nv_bfloat16*)p;
    cudaGetSymbolAddress(&p, g_wdnT_hi); __nv_bfloat16* wdnT_hi = (__nv_bfloat16*)p;
    cudaGetSymbolAddress(&p, g_wdnT_lo); __nv_bfloat16* wdnT_lo = (__nv_bfloat16*)p;
    cudaGetSymbolAddress(&p, g_wsuT_hi); __nv_bfloat16* wsuT_hi = (__nv_bfloat16*)p;
    cudaGetSymbolAddress(&p, g_wsuT_lo); __nv_bfloat16* wsuT_lo = (__nv_bfloat16*)p;
    cudaGetSymbolAddress(&p, g_wsdT_hi); __nv_bfloat16* wsdT_hi = (__nv_bfloat16*)p;
    cudaGetSymbolAddress(&p, g_wsdT_lo); __nv_bfloat16* wsdT_lo = (__nv_bfloat16*)p;
    cudaGetSymbolAddress(&p, g_hsh_hi);  __nv_bfloat16* hsh_hi  = (__nv_bfloat16*)p;
    cudaGetSymbolAddress(&p, g_hsh_lo);  __nv_bfloat16* hsh_lo  = (__nv_bfloat16*)p;
    cudaGetSymbolAddress(&p, g_hrt_hi);  __nv_bfloat16* hrt_hi  = (__nv_bfloat16*)p;
    cudaGetSymbolAddress(&p, g_hrt_lo);  __nv_bfloat16* hrt_lo  = (__nv_bfloat16*)p;
    cudaGetSymbolAddress(&p, g_pair_out); float* pair_out = (float*)p;

    // routing
    zero_counts_kernel<<<1, 32>>>();
    router_kernel<<<NTOK / 4, 128>>>(x, Wr);
    prefix_kernel<<<1, 32>>>();
    scatter_kernel<<<NTOK / 256, 256>>>();

    // operand prep
    split_x_kernel<<<(NTOK * DIM) / (256 * 4), 256>>>(x);
    gather_x_kernel<<<NPAIR, 128>>>();
    {
        dim3 t(32, 8, 1);
        transpose_split_kernel<<<dim3(HDIM / 32, DIM / 32, NEXP), t>>>(Wup, wupT_hi, wupT_lo, DIM, HDIM);
        transpose_split_kernel<<<dim3(DIM / 32, HDIM / 32, NEXP), t>>>(Wdn, wdnT_hi, wdnT_lo, HDIM, DIM);
        transpose_split_kernel<<<dim3(HDIM / 32, DIM / 32, 1), t>>>(Wsu, wsuT_hi, wsuT_lo, DIM, HDIM);
        transpose_split_kernel<<<dim3(DIM / 32, HDIM / 32, 1), t>>>(Wsd, wsdT_hi, wsdT_lo, HDIM, DIM);
    }

    // shared expert
    gemm_mma<0><<<dim3(HDIM / BN, NTOK / BM, 1), 256, GEMM_SMEM>>>(
        x_hi, x_lo, wsuT_hi, wsuT_lo, hsh_hi, hsh_lo, nullptr, DIM, HDIM, 0);
    gemm_mma<1><<<dim3(DIM / BN, NTOK / BM, 1), 256, GEMM_SMEM>>>(
        hsh_hi, hsh_lo, wsdT_hi, wsdT_lo, nullptr, nullptr, out, HDIM, DIM, 0);

    // routed experts (compact pair ordering; grid.y covers worst-case NPAIR rows)
    gemm_mma<0><<<dim3(HDIM / BN, NPAIR / BM, NEXP), 256, GEMM_SMEM>>>(
        xg_hi, xg_lo, wupT_hi, wupT_lo, hrt_hi, hrt_lo, nullptr, DIM, HDIM, 1);
    gemm_mma<1><<<dim3(DIM / BN, NPAIR / BM, NEXP), 256, GEMM_SMEM>>>(
        hrt_hi, hrt_lo, wdnT_hi, wdnT_lo, nullptr, nullptr, pair_out, HDIM, DIM, 1);

    combine_kernel<<<NTOK, 256>>>(out);
}